// round 4
// baseline (speedup 1.0000x reference)
#include <cuda_runtime.h>

#define DIMN 32
#define TPB 256

__device__ unsigned long long g_wp[DIMN];

__device__ __forceinline__ unsigned long long pack2(float lo, float hi) {
    unsigned long long r;
    asm("mov.b64 %0, {%1, %2};" : "=l"(r) : "f"(lo), "f"(hi));
    return r;
}
__device__ __forceinline__ void unpack2(unsigned long long v, float& lo, float& hi) {
    asm("mov.b64 {%0, %1}, %2;" : "=f"(lo), "=f"(hi) : "l"(v));
}
__device__ __forceinline__ unsigned long long fma2(unsigned long long a,
                                                   unsigned long long b,
                                                   unsigned long long c) {
    unsigned long long d;
    asm("fma.rn.f32x2 %0, %1, %2, %3;" : "=l"(d) : "l"(a), "l"(b), "l"(c));
    return d;
}

// Pre-pack (w_k, w_k) pairs once.
__global__ void pack_w_kernel(const float* __restrict__ w) {
    int k = threadIdx.x;
    if (k < DIMN) {
        float wk = w[k];
        g_wp[k] = pack2(wk, wk);
    }
}

// Volatile, un-sinkable coefficient load into a NAMED register variable.
#define LDW(i) \
    unsigned long long w##i; \
    asm volatile("ld.global.nc.b64 %0, [%1];" : "=l"(w##i) : "l"(g_wp + (i)));

// One Horner step across 8 independent packed chains.
#define STEP(WK) \
    a0 = fma2(a0, p0, WK); a1 = fma2(a1, p1, WK); \
    a2 = fma2(a2, p2, WK); a3 = fma2(a3, p3, WK); \
    a4 = fma2(a4, p4, WK); a5 = fma2(a5, p5, WK); \
    a6 = fma2(a6, p6, WK); a7 = fma2(a7, p7, WK);

__global__ __launch_bounds__(TPB) void poly_horner_named_kernel(
    const float* __restrict__ x,
    float* __restrict__ out,
    int n_vec4)
{
    // Block owns TPB*4 consecutive float4s; thread takes 4 strided by TPB.
    int base4 = blockIdx.x * (TPB * 4) + threadIdx.x;

    // ---- all 32 packed coefficients into named registers, pinned ----
    LDW(0)  LDW(1)  LDW(2)  LDW(3)  LDW(4)  LDW(5)  LDW(6)  LDW(7)
    LDW(8)  LDW(9)  LDW(10) LDW(11) LDW(12) LDW(13) LDW(14) LDW(15)
    LDW(16) LDW(17) LDW(18) LDW(19) LDW(20) LDW(21) LDW(22) LDW(23)
    LDW(24) LDW(25) LDW(26) LDW(27) LDW(28) LDW(29) LDW(30) LDW(31)

    // ---- load 16 elements (4x float4, coalesced) ----
    const float4* x4 = reinterpret_cast<const float4*>(x);
    int i0 = base4;
    int i1 = base4 + TPB;
    int i2 = base4 + 2 * TPB;
    int i3 = base4 + 3 * TPB;
    float4 xv0 = (i0 < n_vec4) ? x4[i0] : make_float4(0.f, 0.f, 0.f, 0.f);
    float4 xv1 = (i1 < n_vec4) ? x4[i1] : make_float4(0.f, 0.f, 0.f, 0.f);
    float4 xv2 = (i2 < n_vec4) ? x4[i2] : make_float4(0.f, 0.f, 0.f, 0.f);
    float4 xv3 = (i3 < n_vec4) ? x4[i3] : make_float4(0.f, 0.f, 0.f, 0.f);

    unsigned long long p0 = pack2(xv0.x, xv0.y);
    unsigned long long p1 = pack2(xv0.z, xv0.w);
    unsigned long long p2 = pack2(xv1.x, xv1.y);
    unsigned long long p3 = pack2(xv1.z, xv1.w);
    unsigned long long p4 = pack2(xv2.x, xv2.y);
    unsigned long long p5 = pack2(xv2.z, xv2.w);
    unsigned long long p6 = pack2(xv3.x, xv3.y);
    unsigned long long p7 = pack2(xv3.z, xv3.w);

    unsigned long long a0 = w31, a1 = w31, a2 = w31, a3 = w31;
    unsigned long long a4 = w31, a5 = w31, a6 = w31, a7 = w31;

    // ---- 31 pure-FFMA2 Horner steps ----
    STEP(w30) STEP(w29) STEP(w28) STEP(w27) STEP(w26) STEP(w25) STEP(w24)
    STEP(w23) STEP(w22) STEP(w21) STEP(w20) STEP(w19) STEP(w18) STEP(w17)
    STEP(w16) STEP(w15) STEP(w14) STEP(w13) STEP(w12) STEP(w11) STEP(w10)
    STEP(w9)  STEP(w8)  STEP(w7)  STEP(w6)  STEP(w5)  STEP(w4)  STEP(w3)
    STEP(w2)  STEP(w1)  STEP(w0)

    // ---- store 16 elements ----
    float4* o4 = reinterpret_cast<float4*>(out);
    float4 ov;
    if (i0 < n_vec4) { unpack2(a0, ov.x, ov.y); unpack2(a1, ov.z, ov.w); o4[i0] = ov; }
    if (i1 < n_vec4) { unpack2(a2, ov.x, ov.y); unpack2(a3, ov.z, ov.w); o4[i1] = ov; }
    if (i2 < n_vec4) { unpack2(a4, ov.x, ov.y); unpack2(a5, ov.z, ov.w); o4[i2] = ov; }
    if (i3 < n_vec4) { unpack2(a6, ov.x, ov.y); unpack2(a7, ov.z, ov.w); o4[i3] = ov; }
}

extern "C" void kernel_launch(void* const* d_in, const int* in_sizes, int n_in,
                              void* d_out, int out_size) {
    const float* x = (const float*)d_in[0];
    const float* w = (const float*)d_in[1];
    float* out = (float*)d_out;

    int n = in_sizes[0];            // 4194304
    int n_vec4 = n / 4;             // 1048576 float4s
    int blocks = (n_vec4 + TPB * 4 - 1) / (TPB * 4);  // 1024

    pack_w_kernel<<<1, DIMN>>>(w);
    poly_horner_named_kernel<<<blocks, TPB>>>(x, out, n_vec4);
}

// round 5
// speedup vs baseline: 1.1445x; 1.1445x over previous
#include <cuda_runtime.h>

#define DIMN 32
#define TPB 256
#define CHAINS 8   // 8 f32x2 chains = 16 elements per thread

__device__ unsigned long long g_wp[DIMN];

__device__ __forceinline__ unsigned long long pack2(float lo, float hi) {
    unsigned long long r;
    asm("mov.b64 %0, {%1, %2};" : "=l"(r) : "f"(lo), "f"(hi));
    return r;
}
__device__ __forceinline__ void unpack2(unsigned long long v, float& lo, float& hi) {
    asm("mov.b64 {%0, %1}, %2;" : "=f"(lo), "=f"(hi) : "l"(v));
}
__device__ __forceinline__ unsigned long long fma2(unsigned long long a,
                                                   unsigned long long b,
                                                   unsigned long long c) {
    unsigned long long d;
    asm("fma.rn.f32x2 %0, %1, %2, %3;" : "=l"(d) : "l"(a), "l"(b), "l"(c));
    return d;
}

// Pre-pack (w_k, w_k) pairs once.
__global__ void pack_w_kernel(const float* __restrict__ w) {
    int k = threadIdx.x;
    if (k < DIMN) {
        float wk = w[k];
        g_wp[k] = pack2(wk, wk);
    }
}

__global__ __launch_bounds__(TPB) void poly_horner_smem_kernel(
    const float* __restrict__ x,
    float* __restrict__ out,
    int n_vec4)
{
    // Coefficients staged in shared memory: per-step broadcast LDS.64,
    // off the fma pipe, no register residency needed.
    __shared__ unsigned long long s_wp[DIMN];
    if (threadIdx.x < DIMN) s_wp[threadIdx.x] = g_wp[threadIdx.x];
    __syncthreads();

    // Block owns TPB*4 consecutive float4s; thread takes 4 strided by TPB.
    int base4 = blockIdx.x * (TPB * 4) + threadIdx.x;
    int i0 = base4;
    int i1 = base4 + TPB;
    int i2 = base4 + 2 * TPB;
    int i3 = base4 + 3 * TPB;

    const float4* x4 = reinterpret_cast<const float4*>(x);
    float4 xv0 = (i0 < n_vec4) ? x4[i0] : make_float4(0.f, 0.f, 0.f, 0.f);
    float4 xv1 = (i1 < n_vec4) ? x4[i1] : make_float4(0.f, 0.f, 0.f, 0.f);
    float4 xv2 = (i2 < n_vec4) ? x4[i2] : make_float4(0.f, 0.f, 0.f, 0.f);
    float4 xv3 = (i3 < n_vec4) ? x4[i3] : make_float4(0.f, 0.f, 0.f, 0.f);

    unsigned long long p0 = pack2(xv0.x, xv0.y);
    unsigned long long p1 = pack2(xv0.z, xv0.w);
    unsigned long long p2 = pack2(xv1.x, xv1.y);
    unsigned long long p3 = pack2(xv1.z, xv1.w);
    unsigned long long p4 = pack2(xv2.x, xv2.y);
    unsigned long long p5 = pack2(xv2.z, xv2.w);
    unsigned long long p6 = pack2(xv3.x, xv3.y);
    unsigned long long p7 = pack2(xv3.z, xv3.w);

    unsigned long long a0, a1, a2, a3, a4, a5, a6, a7;
    {
        unsigned long long w31 = s_wp[DIMN - 1];
        a0 = w31; a1 = w31; a2 = w31; a3 = w31;
        a4 = w31; a5 = w31; a6 = w31; a7 = w31;
    }

    // 31 Horner steps; one broadcast LDS.64 per step feeds 8 FFMA2.
#pragma unroll
    for (int k = DIMN - 2; k >= 0; --k) {
        unsigned long long wk = s_wp[k];
        a0 = fma2(a0, p0, wk);
        a1 = fma2(a1, p1, wk);
        a2 = fma2(a2, p2, wk);
        a3 = fma2(a3, p3, wk);
        a4 = fma2(a4, p4, wk);
        a5 = fma2(a5, p5, wk);
        a6 = fma2(a6, p6, wk);
        a7 = fma2(a7, p7, wk);
    }

    float4* o4 = reinterpret_cast<float4*>(out);
    float4 ov;
    if (i0 < n_vec4) { unpack2(a0, ov.x, ov.y); unpack2(a1, ov.z, ov.w); o4[i0] = ov; }
    if (i1 < n_vec4) { unpack2(a2, ov.x, ov.y); unpack2(a3, ov.z, ov.w); o4[i1] = ov; }
    if (i2 < n_vec4) { unpack2(a4, ov.x, ov.y); unpack2(a5, ov.z, ov.w); o4[i2] = ov; }
    if (i3 < n_vec4) { unpack2(a6, ov.x, ov.y); unpack2(a7, ov.z, ov.w); o4[i3] = ov; }
}

extern "C" void kernel_launch(void* const* d_in, const int* in_sizes, int n_in,
                              void* d_out, int out_size) {
    const float* x = (const float*)d_in[0];
    const float* w = (const float*)d_in[1];
    float* out = (float*)d_out;

    int n = in_sizes[0];            // 4194304
    int n_vec4 = n / 4;             // 1048576 float4s
    int blocks = (n_vec4 + TPB * 4 - 1) / (TPB * 4);  // 1024

    pack_w_kernel<<<1, DIMN>>>(w);
    poly_horner_smem_kernel<<<blocks, TPB>>>(x, out, n_vec4);
}